// round 16
// baseline (speedup 1.0000x reference)
#include <cuda_runtime.h>
#include <cuda_bf16.h>
#include <cuda_fp16.h>

#define NN 50000
#define NE 800000
#define NG 128
#define F 64
#define CAP 64    // max stored in-degree; deg ~ Poisson(16), P(>64) ~ 1e-18

// ---- scratch (static device arrays; no allocation) ----
__device__ __align__(16) __half g_xp[NN * F];   // x @ W, fp16 values (logits stay fp32)
__device__ __align__(16) __half g_h[NN * F];    // finalized layer-1 output, fp16
__device__ float g_asrc[NN];
__device__ float g_adst[NN];
__device__ float g_denom[NN];                   // self-loop exp
__device__ int g_gcnt[NG];
__device__ int g_deg[NN];
__device__ int g_csr[NN * CAP];                 // src lists grouped by dst

__device__ __forceinline__ void red_add_v4(float* addr, float a, float b, float c, float d) {
    asm volatile("red.global.add.v4.f32 [%0], {%1,%2,%3,%4};"
                 :: "l"(addr), "f"(a), "f"(b), "f"(c), "f"(d) : "memory");
}

__device__ __forceinline__ unsigned h2bits(__half2 h) {
    return *reinterpret_cast<unsigned*>(&h);
}

__global__ void zero_kernel(float* __restrict__ out) {
    int i = blockIdx.x * blockDim.x + threadIdx.x;
    if (i < NG * F) out[i] = 0.f;
    if (i < NG) g_gcnt[i] = 0;
    if (i < NN) g_deg[i] = 0;
}

// Build by-dst adjacency + per-graph node counts. Once per launch.
__global__ __launch_bounds__(256) void build_kernel(
    const int* __restrict__ src, const int* __restrict__ dst,
    const int* __restrict__ batch)
{
    int t = blockIdx.x * blockDim.x + threadIdx.x;

    if (t < NN / 4) {
        int4 b4 = ((const int4*)batch)[t];
        atomicAdd(&g_gcnt[b4.x], 1);
        atomicAdd(&g_gcnt[b4.y], 1);
        atomicAdd(&g_gcnt[b4.z], 1);
        atomicAdd(&g_gcnt[b4.w], 1);
    }

    if (t >= NE / 4) return;
    int4 s4 = ((const int4*)src)[t];
    int4 d4 = ((const int4*)dst)[t];
    int r;
    r = atomicAdd(&g_deg[d4.x], 1); if (r < CAP) g_csr[d4.x * CAP + r] = s4.x;
    r = atomicAdd(&g_deg[d4.y], 1); if (r < CAP) g_csr[d4.y * CAP + r] = s4.y;
    r = atomicAdd(&g_deg[d4.z], 1); if (r < CAP) g_csr[d4.z * CAP + r] = s4.z;
    r = atomicAdd(&g_deg[d4.w], 1); if (r < CAP) g_csr[d4.w * CAP + r] = s4.w;
}

// Node kernel (register-tiled GEMM, 4 nodes/thread).
// use_x=1: input x fp32 (no PDL dependency); use_x=0: input g_h fp16
// (PDL: Wsm + a-vector loads happen pre-sync, g_h reads post-sync).
__global__ __launch_bounds__(256) void node_kernel(
    const float* __restrict__ x,
    const float* __restrict__ W,
    const float* __restrict__ a_src,
    const float* __restrict__ a_dst,
    int use_x)
{
    __shared__ float4 Wsm[F * 16];   // [k][c] : W[k][4c..4c+3]
    __shared__ float hsm[64 * 65];   // [node][k], padded stride 65

    int tid = threadIdx.x;
    const float4* W4 = (const float4*)W;
    for (int i = tid; i < F * 16; i += 256) Wsm[i] = W4[i];

    int c = tid & 15;
    int g = tid >> 4;
    int base = blockIdx.x * 64;

    float4 as4 = ((const float4*)a_src)[c];
    float4 ad4 = ((const float4*)a_dst)[c];

    // wait for predecessor (agg<0>) before touching g_h
    if (!use_x) cudaGridDependencySynchronize();

    // ---- stage h for 64 nodes ----
    for (int i = tid; i < 1024; i += 256) {
        int node = i >> 4, cc = i & 15;
        int n = base + node;
        float4 v = make_float4(0.f, 0.f, 0.f, 0.f);
        if (n < NN) {
            if (use_x) {
                v = ((const float4*)x)[n * 16 + cc];
            } else {
                uint2 u = ((const uint2*)g_h)[n * 16 + cc];
                float2 f0 = __half22float2(*reinterpret_cast<__half2*>(&u.x));
                float2 f1 = __half22float2(*reinterpret_cast<__half2*>(&u.y));
                v = make_float4(f0.x, f0.y, f1.x, f1.y);
            }
        }
        float* hp = &hsm[node * 65 + cc * 4];
        hp[0] = v.x; hp[1] = v.y; hp[2] = v.z; hp[3] = v.w;
    }
    __syncthreads();

    // ---- GEMM: xp[n][f] = sum_k h[n][k] * W[k][f] ----
    float4 acc0 = make_float4(0.f,0.f,0.f,0.f);
    float4 acc1 = make_float4(0.f,0.f,0.f,0.f);
    float4 acc2 = make_float4(0.f,0.f,0.f,0.f);
    float4 acc3 = make_float4(0.f,0.f,0.f,0.f);
    const float* h0 = &hsm[(g     ) * 65];
    const float* h1 = &hsm[(g + 16) * 65];
    const float* h2 = &hsm[(g + 32) * 65];
    const float* h3 = &hsm[(g + 48) * 65];
#pragma unroll
    for (int k = 0; k < F; ++k) {
        float4 w = Wsm[k * 16 + c];
        float a0 = h0[k], a1 = h1[k], a2 = h2[k], a3 = h3[k];
        acc0.x = fmaf(a0, w.x, acc0.x); acc0.y = fmaf(a0, w.y, acc0.y);
        acc0.z = fmaf(a0, w.z, acc0.z); acc0.w = fmaf(a0, w.w, acc0.w);
        acc1.x = fmaf(a1, w.x, acc1.x); acc1.y = fmaf(a1, w.y, acc1.y);
        acc1.z = fmaf(a1, w.z, acc1.z); acc1.w = fmaf(a1, w.w, acc1.w);
        acc2.x = fmaf(a2, w.x, acc2.x); acc2.y = fmaf(a2, w.y, acc2.y);
        acc2.z = fmaf(a2, w.z, acc2.z); acc2.w = fmaf(a2, w.w, acc2.w);
        acc3.x = fmaf(a3, w.x, acc3.x); acc3.y = fmaf(a3, w.y, acc3.y);
        acc3.z = fmaf(a3, w.z, acc3.z); acc3.w = fmaf(a3, w.w, acc3.w);
    }

    float4 accs[4] = {acc0, acc1, acc2, acc3};
#pragma unroll
    for (int r = 0; r < 4; ++r) {
        float4 a = accs[r];
        float ps = a.x * as4.x + a.y * as4.y + a.z * as4.z + a.w * as4.w;
        float pd = a.x * ad4.x + a.y * ad4.y + a.z * ad4.z + a.w * ad4.w;
#pragma unroll
        for (int o = 1; o < 16; o <<= 1) {
            ps += __shfl_xor_sync(0xffffffffu, ps, o, 16);
            pd += __shfl_xor_sync(0xffffffffu, pd, o, 16);
        }
        int n = base + g + 16 * r;
        if (n < NN) {
            if (c == 0) {
                g_asrc[n] = ps; g_adst[n] = pd;
                float e = ps + pd; e = e > 0.f ? e : 0.2f * e;   // self-loop logit
                g_denom[n] = __expf(e);
            }
            __half2 p0 = __floats2half2_rn(a.x, a.y);
            __half2 p1 = __floats2half2_rn(a.z, a.w);
            uint2 u;
            u.x = h2bits(p0);
            u.y = h2bits(p1);
            ((uint2*)g_xp)[n * 16 + c] = u;
        }
    }
}

// Aggregation + epilogue: 8 lanes per dst node (uint4 = 8 halves per lane),
// 32 nodes per 256-thread block.
// PDL: deg/csr-row/bias loads pre-sync (depend only on build), asrc/xp/denom
// reads post-sync.
// Phase A: branchless 4-slot unroll (deg<=32 fast path, rare tail loop);
//          stage padded with zero-weight entries to a multiple of 4.
// Phase B: unpredicated 4-edge batches; per edge 1 LDG.128 + 4 HFMA2.
template<int FINAL>
__global__ __launch_bounds__(256) void agg_kernel(
    const float* __restrict__ bias, const int* __restrict__ batch,
    float* __restrict__ out)
{
    __shared__ __align__(16) float2 stage[32][CAP + 4];

    int gid = blockIdx.x * blockDim.x + threadIdx.x;
    int n = gid >> 3;
    int grp = threadIdx.x >> 3;         // 0..31
    int lane = threadIdx.x & 7;
    unsigned gmask = 0xFFu << (threadIdx.x & 24);
    if (n >= NN) {
        cudaGridDependencySynchronize();
        return;
    }

    // ---- pre-sync prologue: independent of predecessor node_kernel ----
    int deg = min(g_deg[n], CAP);
    const int* row = &g_csr[n * CAP];
    int s0 = row[lane];
    int s1 = row[lane + 8];
    int s2 = row[lane + 16];
    int s3 = row[lane + 24];
    const float4* b4 = (const float4*)bias;
    float4 bA = b4[lane * 2];
    float4 bB = b4[lane * 2 + 1];

    // wait for node_kernel outputs (asrc/adst/denom/xp)
    cudaGridDependencySynchronize();

    float adstn = g_adst[n];
    float ex_self = g_denom[n];
    const uint4* xp4 = (const uint4*)g_xp;   // 8 halves per lane

    // hoisted long-latency load (overlaps Phase A)
    uint4 su = xp4[n * 8 + lane];

    // ---- Phase A: branchless 4-slot (covers deg<=32), rare tail loop ----
    float dsum = 0.f;
    int padend = (deg + 3) & ~3;
    {
        float a0 = g_asrc[s0];
        float a1 = g_asrc[s1];
        float a2 = g_asrc[s2];
        float a3 = g_asrc[s3];
        float e0 = a0 + adstn; e0 = e0 > 0.f ? e0 : 0.2f * e0;
        float e1 = a1 + adstn; e1 = e1 > 0.f ? e1 : 0.2f * e1;
        float e2 = a2 + adstn; e2 = e2 > 0.f ? e2 : 0.2f * e2;
        float e3 = a3 + adstn; e3 = e3 > 0.f ? e3 : 0.2f * e3;
        float w0 = __expf(e0); if (lane      >= deg) w0 = 0.f;
        float w1 = __expf(e1); if (lane + 8  >= deg) w1 = 0.f;
        float w2 = __expf(e2); if (lane + 16 >= deg) w2 = 0.f;
        float w3 = __expf(e3); if (lane + 24 >= deg) w3 = 0.f;
        dsum += (w0 + w1) + (w2 + w3);
        if (lane < padend)
            stage[grp][lane] = make_float2(__int_as_float(s0),
                __uint_as_float(h2bits(__float2half2_rn(w0))));
        if (lane + 8 < padend)
            stage[grp][lane + 8] = make_float2(__int_as_float(s1),
                __uint_as_float(h2bits(__float2half2_rn(w1))));
        if (lane + 16 < padend)
            stage[grp][lane + 16] = make_float2(__int_as_float(s2),
                __uint_as_float(h2bits(__float2half2_rn(w2))));
        if (lane + 24 < padend)
            stage[grp][lane + 24] = make_float2(__int_as_float(s3),
                __uint_as_float(h2bits(__float2half2_rn(w3))));
    }
    for (int j = lane + 32; j < padend; j += 8) {   // deg>32: rare
        int s = row[j];
        float e = g_asrc[s] + adstn;
        e = e > 0.f ? e : 0.2f * e;
        float w = __expf(e); if (j >= deg) w = 0.f;
        dsum += w;
        stage[grp][j] = make_float2(__int_as_float(s),
            __uint_as_float(h2bits(__float2half2_rn(w))));
    }
    __syncwarp();

    // self-loop feature contribution in fp32 (weight added once after lane-reduction)
    float2 sf0 = __half22float2(*reinterpret_cast<__half2*>(&su.x));
    float2 sf1 = __half22float2(*reinterpret_cast<__half2*>(&su.y));
    float2 sf2 = __half22float2(*reinterpret_cast<__half2*>(&su.z));
    float2 sf3 = __half22float2(*reinterpret_cast<__half2*>(&su.w));
    float4 accA = make_float4(ex_self * sf0.x, ex_self * sf0.y,
                              ex_self * sf1.x, ex_self * sf1.y);
    float4 accB = make_float4(ex_self * sf2.x, ex_self * sf2.y,
                              ex_self * sf3.x, ex_self * sf3.y);

    // ---- Phase B: unpredicated 4-edge batches ----
    const float4* st4 = (const float4*)stage[grp];
    for (int j0 = 0; j0 < deg; j0 += 4) {
        int q = j0 >> 1;
        float4 ee0 = st4[q + 0];   // edges j0, j0+1
        float4 ee1 = st4[q + 1];   // edges j0+2, j0+3

        uint4 v0 = xp4[(unsigned)__float_as_int(ee0.x) * 8u + (unsigned)lane];
        uint4 v1 = xp4[(unsigned)__float_as_int(ee0.z) * 8u + (unsigned)lane];
        uint4 v2 = xp4[(unsigned)__float_as_int(ee1.x) * 8u + (unsigned)lane];
        uint4 v3 = xp4[(unsigned)__float_as_int(ee1.z) * 8u + (unsigned)lane];

        __half2 hA0 = __half2half2(__ushort_as_half(0));
        __half2 hA1 = hA0, hB0 = hA0, hB1 = hA0;
        unsigned wb;
        __half2 wh;
#define ACC_EDGE(wfield, v) \
        wb = __float_as_uint(wfield); \
        wh = *reinterpret_cast<__half2*>(&wb); \
        hA0 = __hfma2(wh, *reinterpret_cast<__half2*>(&(v).x), hA0); \
        hA1 = __hfma2(wh, *reinterpret_cast<__half2*>(&(v).y), hA1); \
        hB0 = __hfma2(wh, *reinterpret_cast<__half2*>(&(v).z), hB0); \
        hB1 = __hfma2(wh, *reinterpret_cast<__half2*>(&(v).w), hB1)
        ACC_EDGE(ee0.y, v0); ACC_EDGE(ee0.w, v1);
        ACC_EDGE(ee1.y, v2); ACC_EDGE(ee1.w, v3);
#undef ACC_EDGE
        float2 fA0 = __half22float2(hA0);
        float2 fA1 = __half22float2(hA1);
        float2 fB0 = __half22float2(hB0);
        float2 fB1 = __half22float2(hB1);
        accA.x += fA0.x; accA.y += fA0.y; accA.z += fA1.x; accA.w += fA1.y;
        accB.x += fB0.x; accB.y += fB0.y; accB.z += fB1.x; accB.w += fB1.y;
    }

#pragma unroll
    for (int o = 1; o < 8; o <<= 1)
        dsum += __shfl_xor_sync(gmask, dsum, o, 8);
    dsum += ex_self;    // self weight counted exactly once

    float dinv = 1.f / dsum;
    float4 hA, hB;
    hA.x = fmaxf(fmaf(accA.x, dinv, bA.x), 0.f);
    hA.y = fmaxf(fmaf(accA.y, dinv, bA.y), 0.f);
    hA.z = fmaxf(fmaf(accA.z, dinv, bA.z), 0.f);
    hA.w = fmaxf(fmaf(accA.w, dinv, bA.w), 0.f);
    hB.x = fmaxf(fmaf(accB.x, dinv, bB.x), 0.f);
    hB.y = fmaxf(fmaf(accB.y, dinv, bB.y), 0.f);
    hB.z = fmaxf(fmaf(accB.z, dinv, bB.z), 0.f);
    hB.w = fmaxf(fmaf(accB.w, dinv, bB.w), 0.f);

    if (FINAL) {
        int g = batch[n];
        float cinv = 1.f / (float)max(g_gcnt[g], 1);
        float* dst = out + g * F + lane * 8;
        red_add_v4(dst,     hA.x * cinv, hA.y * cinv, hA.z * cinv, hA.w * cinv);
        red_add_v4(dst + 4, hB.x * cinv, hB.y * cinv, hB.z * cinv, hB.w * cinv);
    } else {
        uint4 u;
        u.x = h2bits(__floats2half2_rn(hA.x, hA.y));
        u.y = h2bits(__floats2half2_rn(hA.z, hA.w));
        u.z = h2bits(__floats2half2_rn(hB.x, hB.y));
        u.w = h2bits(__floats2half2_rn(hB.z, hB.w));
        ((uint4*)g_h)[n * 8 + lane] = u;
    }
}

// Launch helper: programmatic stream serialization (PDL).
template<typename Fn, typename... Args>
static void launch_pdl(Fn k, int grid, int block, Args... args) {
    cudaLaunchConfig_t cfg = {};
    cfg.gridDim = dim3(grid, 1, 1);
    cfg.blockDim = dim3(block, 1, 1);
    cfg.stream = 0;
    cudaLaunchAttribute attr[1];
    attr[0].id = cudaLaunchAttributeProgrammaticStreamSerialization;
    attr[0].val.programmaticStreamSerializationAllowed = 1;
    cfg.attrs = attr;
    cfg.numAttrs = 1;
    cudaLaunchKernelEx(&cfg, k, args...);
}

extern "C" void kernel_launch(void* const* d_in, const int* in_sizes, int n_in,
                              void* d_out, int out_size) {
    const float* x     = (const float*)d_in[0];
    const int*   ei    = (const int*)d_in[1];     // [2, NE]
    const int*   batch = (const int*)d_in[2];
    const float* W1    = (const float*)d_in[3];
    const float* as1   = (const float*)d_in[4];
    const float* ad1   = (const float*)d_in[5];
    const float* b1    = (const float*)d_in[6];
    const float* W2    = (const float*)d_in[7];
    const float* as2   = (const float*)d_in[8];
    const float* ad2   = (const float*)d_in[9];
    const float* b2    = (const float*)d_in[10];
    float* out = (float*)d_out;

    const int* src = ei;
    const int* dst = ei + NE;

    int node_blocks  = (NN + 63) / 64;            // 782
    int agg_blocks   = (NN * 8 + 255) / 256;      // 1563
    int edge4_blocks = (NE / 4 + 255) / 256;      // 782

    // Side stream + events, created once (outside any capture).
    static cudaStream_t s_side = nullptr;
    static cudaEvent_t ev_fork = nullptr, ev_join = nullptr;
    if (s_side == nullptr) {
        cudaStreamCreateWithFlags(&s_side, cudaStreamNonBlocking);
        cudaEventCreateWithFlags(&ev_fork, cudaEventDisableTiming);
        cudaEventCreateWithFlags(&ev_join, cudaEventDisableTiming);
    }

    // Fork: zero+build (deg/csr/gcnt/out) run concurrently with layer-1
    // node_kernel (touches only x/W1/xp/asrc/adst/denom).
    cudaEventRecord(ev_fork, 0);
    cudaStreamWaitEvent(s_side, ev_fork, 0);
    zero_kernel<<<(NN + 255) / 256, 256, 0, s_side>>>(out);
    build_kernel<<<edge4_blocks, 256, 0, s_side>>>(src, dst, batch);
    cudaEventRecord(ev_join, s_side);

    node_kernel<<<node_blocks, 256>>>(x, W1, as1, ad1, 1);

    // Join before agg<0> (needs csr/deg; out zeroing also complete here).
    cudaStreamWaitEvent(0, ev_join, 0);
    launch_pdl(agg_kernel<0>, agg_blocks, 256, b1, batch, (float*)nullptr);

    // layer 2: PDL overlap — node2 prologue (Wsm) under agg0 tail,
    // agg1 prologue (csr rows) under node2 tail.
    launch_pdl(node_kernel, node_blocks, 256,
               (const float*)nullptr, W2, as2, ad2, 0);
    launch_pdl(agg_kernel<1>, agg_blocks, 256, b2, batch, out);
}

// round 17
// speedup vs baseline: 1.1471x; 1.1471x over previous
#include <cuda_runtime.h>
#include <cuda_bf16.h>
#include <cuda_fp16.h>

#define NN 50000
#define NE 800000
#define NG 128
#define F 64
#define CAP 64    // max stored in-degree; deg ~ Poisson(16), P(>64) ~ 1e-18

// ---- scratch (static device arrays; no allocation) ----
__device__ __align__(16) __half g_xp[NN * F];   // x @ W, fp16 values (logits stay fp32)
__device__ __align__(16) __half g_h[NN * F];    // finalized layer-1 output, fp16
__device__ float g_asrc[NN];
__device__ float g_adst[NN];
__device__ float g_denom[NN];                   // self-loop exp
__device__ int g_gcnt[NG];
__device__ int g_deg[NN];
__device__ int g_csr[NN * CAP];                 // src lists grouped by dst

__device__ __forceinline__ void red_add_v4(float* addr, float a, float b, float c, float d) {
    asm volatile("red.global.add.v4.f32 [%0], {%1,%2,%3,%4};"
                 :: "l"(addr), "f"(a), "f"(b), "f"(c), "f"(d) : "memory");
}

__device__ __forceinline__ unsigned h2bits(__half2 h) {
    return *reinterpret_cast<unsigned*>(&h);
}

__global__ void zero_kernel(float* __restrict__ out) {
    int i = blockIdx.x * blockDim.x + threadIdx.x;
    if (i < NG * F) out[i] = 0.f;
    if (i < NG) g_gcnt[i] = 0;
    if (i < NN) g_deg[i] = 0;
}

// Build by-dst adjacency + per-graph node counts. Once per launch.
__global__ __launch_bounds__(256) void build_kernel(
    const int* __restrict__ src, const int* __restrict__ dst,
    const int* __restrict__ batch)
{
    int t = blockIdx.x * blockDim.x + threadIdx.x;

    if (t < NN / 4) {
        int4 b4 = ((const int4*)batch)[t];
        atomicAdd(&g_gcnt[b4.x], 1);
        atomicAdd(&g_gcnt[b4.y], 1);
        atomicAdd(&g_gcnt[b4.z], 1);
        atomicAdd(&g_gcnt[b4.w], 1);
    }

    if (t >= NE / 4) return;
    int4 s4 = ((const int4*)src)[t];
    int4 d4 = ((const int4*)dst)[t];
    int r;
    r = atomicAdd(&g_deg[d4.x], 1); if (r < CAP) g_csr[d4.x * CAP + r] = s4.x;
    r = atomicAdd(&g_deg[d4.y], 1); if (r < CAP) g_csr[d4.y * CAP + r] = s4.y;
    r = atomicAdd(&g_deg[d4.z], 1); if (r < CAP) g_csr[d4.z * CAP + r] = s4.z;
    r = atomicAdd(&g_deg[d4.w], 1); if (r < CAP) g_csr[d4.w * CAP + r] = s4.w;
}

// Node kernel (register-tiled GEMM, 4 nodes/thread).
// use_x=1: input x fp32 (no PDL dependency); use_x=0: input g_h fp16
// (PDL: Wsm + a-vector loads happen pre-sync, g_h reads post-sync).
__global__ __launch_bounds__(256) void node_kernel(
    const float* __restrict__ x,
    const float* __restrict__ W,
    const float* __restrict__ a_src,
    const float* __restrict__ a_dst,
    int use_x)
{
    __shared__ float4 Wsm[F * 16];   // [k][c] : W[k][4c..4c+3]
    __shared__ float hsm[64 * 65];   // [node][k], padded stride 65

    int tid = threadIdx.x;
    const float4* W4 = (const float4*)W;
    for (int i = tid; i < F * 16; i += 256) Wsm[i] = W4[i];

    int c = tid & 15;
    int g = tid >> 4;
    int base = blockIdx.x * 64;

    float4 as4 = ((const float4*)a_src)[c];
    float4 ad4 = ((const float4*)a_dst)[c];

    // wait for predecessor (agg<0>) before touching g_h
    if (!use_x) cudaGridDependencySynchronize();

    // ---- stage h for 64 nodes ----
    for (int i = tid; i < 1024; i += 256) {
        int node = i >> 4, cc = i & 15;
        int n = base + node;
        float4 v = make_float4(0.f, 0.f, 0.f, 0.f);
        if (n < NN) {
            if (use_x) {
                v = ((const float4*)x)[n * 16 + cc];
            } else {
                uint2 u = ((const uint2*)g_h)[n * 16 + cc];
                float2 f0 = __half22float2(*reinterpret_cast<__half2*>(&u.x));
                float2 f1 = __half22float2(*reinterpret_cast<__half2*>(&u.y));
                v = make_float4(f0.x, f0.y, f1.x, f1.y);
            }
        }
        float* hp = &hsm[node * 65 + cc * 4];
        hp[0] = v.x; hp[1] = v.y; hp[2] = v.z; hp[3] = v.w;
    }
    __syncthreads();

    // ---- GEMM: xp[n][f] = sum_k h[n][k] * W[k][f] ----
    float4 acc0 = make_float4(0.f,0.f,0.f,0.f);
    float4 acc1 = make_float4(0.f,0.f,0.f,0.f);
    float4 acc2 = make_float4(0.f,0.f,0.f,0.f);
    float4 acc3 = make_float4(0.f,0.f,0.f,0.f);
    const float* h0 = &hsm[(g     ) * 65];
    const float* h1 = &hsm[(g + 16) * 65];
    const float* h2 = &hsm[(g + 32) * 65];
    const float* h3 = &hsm[(g + 48) * 65];
#pragma unroll
    for (int k = 0; k < F; ++k) {
        float4 w = Wsm[k * 16 + c];
        float a0 = h0[k], a1 = h1[k], a2 = h2[k], a3 = h3[k];
        acc0.x = fmaf(a0, w.x, acc0.x); acc0.y = fmaf(a0, w.y, acc0.y);
        acc0.z = fmaf(a0, w.z, acc0.z); acc0.w = fmaf(a0, w.w, acc0.w);
        acc1.x = fmaf(a1, w.x, acc1.x); acc1.y = fmaf(a1, w.y, acc1.y);
        acc1.z = fmaf(a1, w.z, acc1.z); acc1.w = fmaf(a1, w.w, acc1.w);
        acc2.x = fmaf(a2, w.x, acc2.x); acc2.y = fmaf(a2, w.y, acc2.y);
        acc2.z = fmaf(a2, w.z, acc2.z); acc2.w = fmaf(a2, w.w, acc2.w);
        acc3.x = fmaf(a3, w.x, acc3.x); acc3.y = fmaf(a3, w.y, acc3.y);
        acc3.z = fmaf(a3, w.z, acc3.z); acc3.w = fmaf(a3, w.w, acc3.w);
    }

    float4 accs[4] = {acc0, acc1, acc2, acc3};
#pragma unroll
    for (int r = 0; r < 4; ++r) {
        float4 a = accs[r];
        float ps = a.x * as4.x + a.y * as4.y + a.z * as4.z + a.w * as4.w;
        float pd = a.x * ad4.x + a.y * ad4.y + a.z * ad4.z + a.w * ad4.w;
#pragma unroll
        for (int o = 1; o < 16; o <<= 1) {
            ps += __shfl_xor_sync(0xffffffffu, ps, o, 16);
            pd += __shfl_xor_sync(0xffffffffu, pd, o, 16);
        }
        int n = base + g + 16 * r;
        if (n < NN) {
            if (c == 0) {
                g_asrc[n] = ps; g_adst[n] = pd;
                float e = ps + pd; e = e > 0.f ? e : 0.2f * e;   // self-loop logit
                g_denom[n] = __expf(e);
            }
            __half2 p0 = __floats2half2_rn(a.x, a.y);
            __half2 p1 = __floats2half2_rn(a.z, a.w);
            uint2 u;
            u.x = h2bits(p0);
            u.y = h2bits(p1);
            ((uint2*)g_xp)[n * 16 + c] = u;
        }
    }
}

// Aggregation + epilogue: 16 lanes per dst node, 8 nodes per 128-thread block
// (small blocks -> finer load balancing across the deg distribution).
// PDL: deg/csr-row/bias loads pre-sync (depend only on build), asrc/xp/denom
// reads post-sync.
template<int FINAL>
__global__ __launch_bounds__(128) void agg_kernel(
    const float* __restrict__ bias, const int* __restrict__ batch,
    float* __restrict__ out)
{
    __shared__ __align__(16) float2 stage[8][CAP + 8];

    int gid = blockIdx.x * blockDim.x + threadIdx.x;
    int n = gid >> 4;
    int grp = threadIdx.x >> 4;         // 0..7
    int lane = threadIdx.x & 15;
    unsigned gmask = 0xFFFFu << (threadIdx.x & 16);
    if (n >= NN) {
        cudaGridDependencySynchronize();
        return;
    }

    // ---- pre-sync prologue: independent of predecessor node_kernel ----
    int deg = min(g_deg[n], CAP);
    const int* row = &g_csr[n * CAP];
    int s0 = row[lane];
    int s1 = row[lane + 16];
    float4 b = ((const float4*)bias)[lane];

    // wait for node_kernel outputs (asrc/adst/denom/xp)
    cudaGridDependencySynchronize();

    float adstn = g_adst[n];
    float ex_self = g_denom[n];
    const uint2* xp2 = (const uint2*)g_xp;   // 4 halves per lane

    // hoisted long-latency load (overlaps Phase A)
    uint2 su = xp2[n * 16 + lane];

    // ---- Phase A: branchless 2-slot (covers deg<=32), rare tail loop ----
    float dsum = 0.f;
    int padend = (deg + 7) & ~7;
    {
        float a0 = g_asrc[s0];
        float a1 = g_asrc[s1];
        float e0 = a0 + adstn; e0 = e0 > 0.f ? e0 : 0.2f * e0;
        float e1 = a1 + adstn; e1 = e1 > 0.f ? e1 : 0.2f * e1;
        float w0 = __expf(e0); if (lane      >= deg) w0 = 0.f;
        float w1 = __expf(e1); if (lane + 16 >= deg) w1 = 0.f;
        dsum += w0 + w1;
        if (lane < padend)
            stage[grp][lane] = make_float2(__int_as_float(s0),
                                           __uint_as_float(h2bits(__float2half2_rn(w0))));
        if (lane + 16 < padend)
            stage[grp][lane + 16] = make_float2(__int_as_float(s1),
                                                __uint_as_float(h2bits(__float2half2_rn(w1))));
    }
    for (int j = lane + 32; j < padend; j += 16) {   // deg>32: rare
        int s = row[j];
        float e = g_asrc[s] + adstn;
        e = e > 0.f ? e : 0.2f * e;
        float w = __expf(e); if (j >= deg) w = 0.f;
        dsum += w;
        stage[grp][j] = make_float2(__int_as_float(s),
                                    __uint_as_float(h2bits(__float2half2_rn(w))));
    }
    __syncwarp();

    // self-loop feature contribution in fp32 (weight added once after lane-reduction)
    float2 s0f = __half22float2(*reinterpret_cast<__half2*>(&su.x));
    float2 s1f = __half22float2(*reinterpret_cast<__half2*>(&su.y));
    float4 acc = make_float4(ex_self * s0f.x, ex_self * s0f.y,
                             ex_self * s1f.x, ex_self * s1f.y);

    // ---- Phase B: unpredicated 8-edge batches ----
    const float4* st4 = (const float4*)stage[grp];
    for (int j0 = 0; j0 < deg; j0 += 8) {
        int q = j0 >> 1;
        float4 ee0 = st4[q + 0];
        float4 ee1 = st4[q + 1];
        float4 ee2 = st4[q + 2];
        float4 ee3 = st4[q + 3];

        uint2 v0 = xp2[(unsigned)__float_as_int(ee0.x) * 16u + (unsigned)lane];
        uint2 v1 = xp2[(unsigned)__float_as_int(ee0.z) * 16u + (unsigned)lane];
        uint2 v2 = xp2[(unsigned)__float_as_int(ee1.x) * 16u + (unsigned)lane];
        uint2 v3 = xp2[(unsigned)__float_as_int(ee1.z) * 16u + (unsigned)lane];
        uint2 v4 = xp2[(unsigned)__float_as_int(ee2.x) * 16u + (unsigned)lane];
        uint2 v5 = xp2[(unsigned)__float_as_int(ee2.z) * 16u + (unsigned)lane];
        uint2 v6 = xp2[(unsigned)__float_as_int(ee3.x) * 16u + (unsigned)lane];
        uint2 v7 = xp2[(unsigned)__float_as_int(ee3.z) * 16u + (unsigned)lane];

        __half2 h0 = __half2half2(__ushort_as_half(0));
        __half2 h1 = h0;
        unsigned wb;
        __half2 wh;
#define ACC_EDGE(wfield, v) \
        wb = __float_as_uint(wfield); \
        wh = *reinterpret_cast<__half2*>(&wb); \
        h0 = __hfma2(wh, *reinterpret_cast<__half2*>(&(v).x), h0); \
        h1 = __hfma2(wh, *reinterpret_cast<__half2*>(&(v).y), h1)
        ACC_EDGE(ee0.y, v0); ACC_EDGE(ee0.w, v1);
        ACC_EDGE(ee1.y, v2); ACC_EDGE(ee1.w, v3);
        ACC_EDGE(ee2.y, v4); ACC_EDGE(ee2.w, v5);
        ACC_EDGE(ee3.y, v6); ACC_EDGE(ee3.w, v7);
#undef ACC_EDGE
        float2 f0 = __half22float2(h0);
        float2 f1 = __half22float2(h1);
        acc.x += f0.x; acc.y += f0.y;
        acc.z += f1.x; acc.w += f1.y;
    }

#pragma unroll
    for (int o = 1; o < 16; o <<= 1)
        dsum += __shfl_xor_sync(gmask, dsum, o, 16);
    dsum += ex_self;    // self weight counted exactly once

    float dinv = 1.f / dsum;
    float4 h;
    h.x = fmaxf(fmaf(acc.x, dinv, b.x), 0.f);
    h.y = fmaxf(fmaf(acc.y, dinv, b.y), 0.f);
    h.z = fmaxf(fmaf(acc.z, dinv, b.z), 0.f);
    h.w = fmaxf(fmaf(acc.w, dinv, b.w), 0.f);

    if (FINAL) {
        int g = batch[n];
        float cinv = 1.f / (float)max(g_gcnt[g], 1);
        red_add_v4(out + (g * 16 + lane) * 4,
                   h.x * cinv, h.y * cinv, h.z * cinv, h.w * cinv);
    } else {
        __half2 p0 = __floats2half2_rn(h.x, h.y);
        __half2 p1 = __floats2half2_rn(h.z, h.w);
        uint2 u;
        u.x = h2bits(p0);
        u.y = h2bits(p1);
        ((uint2*)g_h)[n * 16 + lane] = u;
    }
}

// Launch helper: programmatic stream serialization (PDL).
template<typename Fn, typename... Args>
static void launch_pdl(Fn k, int grid, int block, Args... args) {
    cudaLaunchConfig_t cfg = {};
    cfg.gridDim = dim3(grid, 1, 1);
    cfg.blockDim = dim3(block, 1, 1);
    cfg.stream = 0;
    cudaLaunchAttribute attr[1];
    attr[0].id = cudaLaunchAttributeProgrammaticStreamSerialization;
    attr[0].val.programmaticStreamSerializationAllowed = 1;
    cfg.attrs = attr;
    cfg.numAttrs = 1;
    cudaLaunchKernelEx(&cfg, k, args...);
}

extern "C" void kernel_launch(void* const* d_in, const int* in_sizes, int n_in,
                              void* d_out, int out_size) {
    const float* x     = (const float*)d_in[0];
    const int*   ei    = (const int*)d_in[1];     // [2, NE]
    const int*   batch = (const int*)d_in[2];
    const float* W1    = (const float*)d_in[3];
    const float* as1   = (const float*)d_in[4];
    const float* ad1   = (const float*)d_in[5];
    const float* b1    = (const float*)d_in[6];
    const float* W2    = (const float*)d_in[7];
    const float* as2   = (const float*)d_in[8];
    const float* ad2   = (const float*)d_in[9];
    const float* b2    = (const float*)d_in[10];
    float* out = (float*)d_out;

    const int* src = ei;
    const int* dst = ei + NE;

    int node_blocks  = (NN + 63) / 64;            // 782
    int agg_blocks   = (NN * 16 + 127) / 128;     // 6250
    int edge4_blocks = (NE / 4 + 255) / 256;      // 782

    // Side stream + events, created once (outside any capture).
    static cudaStream_t s_side = nullptr;
    static cudaEvent_t ev_fork = nullptr, ev_join = nullptr;
    if (s_side == nullptr) {
        cudaStreamCreateWithFlags(&s_side, cudaStreamNonBlocking);
        cudaEventCreateWithFlags(&ev_fork, cudaEventDisableTiming);
        cudaEventCreateWithFlags(&ev_join, cudaEventDisableTiming);
    }

    // Fork: zero+build (deg/csr/gcnt/out) run concurrently with layer-1
    // node_kernel (touches only x/W1/xp/asrc/adst/denom).
    cudaEventRecord(ev_fork, 0);
    cudaStreamWaitEvent(s_side, ev_fork, 0);
    zero_kernel<<<(NN + 255) / 256, 256, 0, s_side>>>(out);
    build_kernel<<<edge4_blocks, 256, 0, s_side>>>(src, dst, batch);
    cudaEventRecord(ev_join, s_side);

    node_kernel<<<node_blocks, 256>>>(x, W1, as1, ad1, 1);

    // Join before agg<0> (needs csr/deg; out zeroing also complete here).
    cudaStreamWaitEvent(0, ev_join, 0);
    launch_pdl(agg_kernel<0>, agg_blocks, 128, b1, batch, (float*)nullptr);

    // layer 2: PDL overlap — node2 prologue (Wsm) under agg0 tail,
    // agg1 prologue (csr rows) under node2 tail.
    launch_pdl(node_kernel, node_blocks, 256,
               (const float*)nullptr, W2, as2, ad2, 0);
    launch_pdl(agg_kernel<1>, agg_blocks, 128, b2, batch, out);
}